// round 1
// baseline (speedup 1.0000x reference)
#include <cuda_runtime.h>

// LightGCN 3-layer propagation on bipartite graph + batched lookup.
// Inputs (metadata order):
//  0: user_feat f32 [200000*64]
//  1: item_feat f32 [100000*64]
//  2: edge_u    i32 [1000000]
//  3: edge_i    i32 [1000000]
//  4: norm      f32 [1000000]
//  5: users     i32 [8192]
//  6: pos_items i32 [8192]
//  7: neg_items i32 [8192]
// Output: f32 [3*8192*64] = concat(u_acc[users], i_acc[pos], i_acc[neg]) * 0.25

constexpr int N_USERS = 200000;
constexpr int N_ITEMS = 100000;
constexpr int N_EDGES = 1000000;
constexpr int DV      = 16;        // 64 floats = 16 float4
constexpr int BATCH   = 8192;

constexpr int NU4 = N_USERS * DV;  // 3,200,000 float4
constexpr int NI4 = N_ITEMS * DV;  // 1,600,000 float4

// Static scratch (~230MB total) — allowed; no runtime allocation.
__device__ float4 g_u[2][NU4];
__device__ float4 g_i[2][NI4];
__device__ float4 g_uacc[NU4];
__device__ float4 g_iacc[NI4];

__device__ __forceinline__ void red4(float4* p, float x, float y, float z, float w) {
    asm volatile("red.global.add.v4.f32 [%0], {%1,%2,%3,%4};"
                 :: "l"(p), "f"(x), "f"(y), "f"(z), "f"(w)
                 : "memory");
}

// init: cur(ping=0) = feat, acc = feat, next(ping=1) = 0
__global__ void k_init(const float4* __restrict__ uf, const float4* __restrict__ itf) {
    int t = blockIdx.x * blockDim.x + threadIdx.x;
    const float4 z = make_float4(0.f, 0.f, 0.f, 0.f);
    if (t < NU4) {
        float4 v = uf[t];
        g_u[0][t] = v;
        g_uacc[t] = v;
        g_u[1][t] = z;
    } else if (t < NU4 + NI4) {
        int k = t - NU4;
        float4 v = itf[k];
        g_i[0][k] = v;
        g_iacc[k] = v;
        g_i[1][k] = z;
    }
}

// One layer of propagation, both directions fused. 16 lanes per edge.
__global__ void k_scatter(const int* __restrict__ eu, const int* __restrict__ ei,
                          const float* __restrict__ nrm, int ping) {
    long long t = (long long)blockIdx.x * blockDim.x + threadIdx.x;
    int e = (int)(t >> 4);
    int lane = (int)(t & 15);
    if (e >= N_EDGES) return;

    int u = __ldg(eu + e);
    int i = __ldg(ei + e);
    float w = __ldg(nrm + e);

    const float4* ucur = g_u[ping];
    const float4* icur = g_i[ping];
    float4* unext = g_u[ping ^ 1];
    float4* inext = g_i[ping ^ 1];

    float4 ur = ucur[u * DV + lane];
    float4 ir = icur[i * DV + lane];

    red4(&inext[i * DV + lane], ur.x * w, ur.y * w, ur.z * w, ur.w * w);
    red4(&unext[u * DV + lane], ir.x * w, ir.y * w, ir.z * w, ir.w * w);
}

// acc += g[nxt];  optionally zero g[nxt^1] (the buffer reused as next layer's target)
__global__ void k_acczero(int nxt, int zero_old) {
    int t = blockIdx.x * blockDim.x + threadIdx.x;
    const float4 z = make_float4(0.f, 0.f, 0.f, 0.f);
    if (t < NU4) {
        float4 a = g_uacc[t];
        float4 b = g_u[nxt][t];
        g_uacc[t] = make_float4(a.x + b.x, a.y + b.y, a.z + b.z, a.w + b.w);
        if (zero_old) g_u[nxt ^ 1][t] = z;
    } else if (t < NU4 + NI4) {
        int k = t - NU4;
        float4 a = g_iacc[k];
        float4 b = g_i[nxt][k];
        g_iacc[k] = make_float4(a.x + b.x, a.y + b.y, a.z + b.z, a.w + b.w);
        if (zero_old) g_i[nxt ^ 1][k] = z;
    }
}

__global__ void k_gather(const int* __restrict__ users, const int* __restrict__ pos,
                         const int* __restrict__ neg, float4* __restrict__ out) {
    int t = blockIdx.x * blockDim.x + threadIdx.x;
    const int total = 3 * BATCH * DV;
    if (t >= total) return;
    int sec  = t / (BATCH * DV);
    int rem  = t % (BATCH * DV);
    int r    = rem / DV;
    int lane = rem % DV;

    float4 v;
    if (sec == 0)      v = g_uacc[__ldg(users + r) * DV + lane];
    else if (sec == 1) v = g_iacc[__ldg(pos + r)   * DV + lane];
    else               v = g_iacc[__ldg(neg + r)   * DV + lane];

    const float s = 0.25f;  // 1/(NUM_LAYERS+1)
    out[t] = make_float4(v.x * s, v.y * s, v.z * s, v.w * s);
}

extern "C" void kernel_launch(void* const* d_in, const int* in_sizes, int n_in,
                              void* d_out, int out_size) {
    const float4* user_feat = (const float4*)d_in[0];
    const float4* item_feat = (const float4*)d_in[1];
    const int*    edge_u    = (const int*)d_in[2];
    const int*    edge_i    = (const int*)d_in[3];
    const float*  nrm       = (const float*)d_in[4];
    const int*    users     = (const int*)d_in[5];
    const int*    pos       = (const int*)d_in[6];
    const int*    neg       = (const int*)d_in[7];
    float4*       out       = (float4*)d_out;

    const int TPB = 256;
    const int dense_total = NU4 + NI4;                      // 4.8M threads
    const int dense_blocks = (dense_total + TPB - 1) / TPB;
    const long long sc_threads = (long long)N_EDGES * DV;   // 16M threads
    const int sc_blocks = (int)((sc_threads + TPB - 1) / TPB);
    const int gt_total = 3 * BATCH * DV;
    const int gt_blocks = (gt_total + TPB - 1) / TPB;

    k_init<<<dense_blocks, TPB>>>(user_feat, item_feat);

    int ping = 0;
    for (int l = 0; l < 3; l++) {
        k_scatter<<<sc_blocks, TPB>>>(edge_u, edge_i, nrm, ping);
        k_acczero<<<dense_blocks, TPB>>>(ping ^ 1, (l < 2) ? 1 : 0);
        ping ^= 1;
    }

    k_gather<<<gt_blocks, TPB>>>(users, pos, neg, out);
}

// round 2
// speedup vs baseline: 1.3207x; 1.3207x over previous
#include <cuda_runtime.h>

// LightGCN 3-layer propagation + batched lookup.
// Round 2: (a) lazy accumulation — keep h1,h2,h3, sum only at final gather
//          (b) feature-dim split (2 halves of 32 floats) so each scatter
//              pass's working set (~89MB) fits the 126MB L2.

constexpr int N_USERS = 200000;
constexpr int N_ITEMS = 100000;
constexpr int N_EDGES = 1000000;
constexpr int DV      = 16;        // 64 floats = 16 float4
constexpr int HV      = 8;         // half-D = 8 float4
constexpr int BATCH   = 8192;

constexpr int NU4 = N_USERS * DV;  // 3,200,000 float4
constexpr int NI4 = N_ITEMS * DV;  // 1,600,000 float4

// Layer outputs h1..h3 (~307MB static; allowed).
__device__ float4 g_u[3][NU4];
__device__ float4 g_i[3][NI4];

__device__ __forceinline__ void red4(float4* p, float x, float y, float z, float w) {
    asm volatile("red.global.add.v4.f32 [%0], {%1,%2,%3,%4};"
                 :: "l"(p), "f"(x), "f"(y), "f"(z), "f"(w)
                 : "memory");
}

// Zero all three layer buffers (atomics need zeroed targets).
__global__ void k_zero() {
    int t = blockIdx.x * blockDim.x + threadIdx.x;
    const float4 z = make_float4(0.f, 0.f, 0.f, 0.f);
    if (t < NU4) {
        g_u[0][t] = z; g_u[1][t] = z; g_u[2][t] = z;
    } else if (t < NU4 + NI4) {
        int k = t - NU4;
        g_i[0][k] = z; g_i[1][k] = z; g_i[2][k] = z;
    }
}

// One propagation layer, one D-half, both directions fused. 8 lanes per edge.
// layer 0 reads the input feature tables directly (h0).
__global__ void k_scatter(const float4* __restrict__ uf, const float4* __restrict__ itf,
                          const int* __restrict__ eu, const int* __restrict__ ei,
                          const float* __restrict__ nrm, int layer, int half) {
    long long t = (long long)blockIdx.x * blockDim.x + threadIdx.x;
    int e = (int)(t >> 3);
    int lane = (int)(t & 7) + half * HV;
    if (e >= N_EDGES) return;

    int u = __ldg(eu + e);
    int i = __ldg(ei + e);
    float w = __ldg(nrm + e);

    const float4* ucur = (layer == 0) ? uf  : g_u[layer - 1];
    const float4* icur = (layer == 0) ? itf : g_i[layer - 1];
    float4* unext = g_u[layer];
    float4* inext = g_i[layer];

    float4 ur = ucur[u * DV + lane];
    float4 ir = icur[i * DV + lane];

    red4(&inext[i * DV + lane], ur.x * w, ur.y * w, ur.z * w, ur.w * w);
    red4(&unext[u * DV + lane], ir.x * w, ir.y * w, ir.z * w, ir.w * w);
}

// out = 0.25 * (h0 + h1 + h2 + h3)[idx]
__global__ void k_gather(const float4* __restrict__ uf, const float4* __restrict__ itf,
                         const int* __restrict__ users, const int* __restrict__ pos,
                         const int* __restrict__ neg, float4* __restrict__ out) {
    int t = blockIdx.x * blockDim.x + threadIdx.x;
    const int total = 3 * BATCH * DV;
    if (t >= total) return;
    int sec  = t / (BATCH * DV);
    int rem  = t % (BATCH * DV);
    int r    = rem / DV;
    int lane = rem % DV;

    float4 acc;
    if (sec == 0) {
        int idx = __ldg(users + r) * DV + lane;
        float4 a = uf[idx], b = g_u[0][idx], c = g_u[1][idx], d = g_u[2][idx];
        acc = make_float4(a.x + b.x + c.x + d.x, a.y + b.y + c.y + d.y,
                          a.z + b.z + c.z + d.z, a.w + b.w + c.w + d.w);
    } else {
        int idx = ((sec == 1) ? __ldg(pos + r) : __ldg(neg + r)) * DV + lane;
        float4 a = itf[idx], b = g_i[0][idx], c = g_i[1][idx], d = g_i[2][idx];
        acc = make_float4(a.x + b.x + c.x + d.x, a.y + b.y + c.y + d.y,
                          a.z + b.z + c.z + d.z, a.w + b.w + c.w + d.w);
    }

    const float s = 0.25f;  // 1/(NUM_LAYERS+1)
    out[t] = make_float4(acc.x * s, acc.y * s, acc.z * s, acc.w * s);
}

extern "C" void kernel_launch(void* const* d_in, const int* in_sizes, int n_in,
                              void* d_out, int out_size) {
    const float4* user_feat = (const float4*)d_in[0];
    const float4* item_feat = (const float4*)d_in[1];
    const int*    edge_u    = (const int*)d_in[2];
    const int*    edge_i    = (const int*)d_in[3];
    const float*  nrm       = (const float*)d_in[4];
    const int*    users     = (const int*)d_in[5];
    const int*    pos       = (const int*)d_in[6];
    const int*    neg       = (const int*)d_in[7];
    float4*       out       = (float4*)d_out;

    const int TPB = 256;
    const int zero_total  = NU4 + NI4;
    const int zero_blocks = (zero_total + TPB - 1) / TPB;
    const long long sc_threads = (long long)N_EDGES * HV;   // 8M per half-pass
    const int sc_blocks = (int)((sc_threads + TPB - 1) / TPB);
    const int gt_total  = 3 * BATCH * DV;
    const int gt_blocks = (gt_total + TPB - 1) / TPB;

    k_zero<<<zero_blocks, TPB>>>();

    for (int l = 0; l < 3; l++) {
        k_scatter<<<sc_blocks, TPB>>>(user_feat, item_feat, edge_u, edge_i, nrm, l, 0);
        k_scatter<<<sc_blocks, TPB>>>(user_feat, item_feat, edge_u, edge_i, nrm, l, 1);
    }

    k_gather<<<gt_blocks, TPB>>>(user_feat, item_feat, users, pos, neg, out);
}

// round 3
// speedup vs baseline: 1.6670x; 1.2622x over previous
#include <cuda_runtime.h>

// LightGCN 3-layer propagation + batched lookup — Round 3: CSR gather.
// Build combined CSR (users then items as destinations) on device each call,
// then each layer is an atomic-free gather-sum per destination node.

constexpr int N_USERS = 200000;
constexpr int N_ITEMS = 100000;
constexpr int N_EDGES = 1000000;
constexpr int NT      = N_USERS + N_ITEMS;   // 300,000 destination nodes
constexpr int DV      = 16;                  // 64 floats = 16 float4
constexpr int BATCH   = 8192;

constexpr int NU4 = N_USERS * DV;
constexpr int NI4 = N_ITEMS * DV;

constexpr int SCAN_TPB   = 256;
constexpr int SCAN_ELEMS = 8;                // 2048 per block
constexpr int SCAN_TILE  = SCAN_TPB * SCAN_ELEMS;
constexpr int NB         = (NT + SCAN_TILE - 1) / SCAN_TILE;  // 147

// Static scratch (~250MB total).
__device__ float4 g_u[3][NU4];
__device__ float4 g_i[3][NI4];
__device__ int    g_cnt[NT];
__device__ int    g_off[NT + 1];
__device__ int    g_cur[NT];
__device__ int    g_bsum[NB];
__device__ int2   g_csr[2 * N_EDGES];        // .x = src node, .y = weight bits

// ---------------- preprocessing ----------------

__global__ void k_zero_cnt() {
    int t = blockIdx.x * blockDim.x + threadIdx.x;
    if (t < NT) g_cnt[t] = 0;
}

__global__ void k_hist(const int* __restrict__ eu, const int* __restrict__ ei) {
    int e = blockIdx.x * blockDim.x + threadIdx.x;
    if (e >= N_EDGES) return;
    atomicAdd(&g_cnt[__ldg(eu + e)], 1);
    atomicAdd(&g_cnt[N_USERS + __ldg(ei + e)], 1);
}

// exclusive scan of v across 256 threads; *total gets block sum
__device__ __forceinline__ int block_exscan(int v, int tid, int* total) {
    __shared__ int wsum[8];
    __shared__ int sh_total;
    int lane = tid & 31, wid = tid >> 5;
    int x = v;
    #pragma unroll
    for (int o = 1; o < 32; o <<= 1) {
        int y = __shfl_up_sync(0xffffffffu, x, o);
        if (lane >= o) x += y;
    }
    if (lane == 31) wsum[wid] = x;           // inclusive warp totals
    __syncthreads();
    if (wid == 0) {
        int t8 = (lane < 8) ? wsum[lane] : 0;
        int s = t8;
        #pragma unroll
        for (int o = 1; o < 8; o <<= 1) {
            int y = __shfl_up_sync(0xffffffffu, s, o);
            if (lane >= o) s += y;
        }
        if (lane < 8) wsum[lane] = s - t8;   // exclusive warp bases
        if (lane == 7) sh_total = s;
    }
    __syncthreads();
    int excl = wsum[wid] + (x - v);
    *total = sh_total;
    return excl;
}

__global__ void k_scan1() {
    int tid = threadIdx.x;
    int base = blockIdx.x * SCAN_TILE + tid * SCAN_ELEMS;
    int vals[SCAN_ELEMS];
    if (base < NT) {                          // NT % 8 == 0 -> whole group valid
        int4 a = *(const int4*)&g_cnt[base];
        int4 b = *(const int4*)&g_cnt[base + 4];
        vals[0]=a.x; vals[1]=a.y; vals[2]=a.z; vals[3]=a.w;
        vals[4]=b.x; vals[5]=b.y; vals[6]=b.z; vals[7]=b.w;
    } else {
        #pragma unroll
        for (int k = 0; k < SCAN_ELEMS; k++) vals[k] = 0;
    }
    int tsum = 0;
    #pragma unroll
    for (int k = 0; k < SCAN_ELEMS; k++) tsum += vals[k];
    int total;
    int tbase = block_exscan(tsum, tid, &total);
    if (base < NT) {
        int run = tbase;
        int outv[SCAN_ELEMS];
        #pragma unroll
        for (int k = 0; k < SCAN_ELEMS; k++) { outv[k] = run; run += vals[k]; }
        *(int4*)&g_off[base]     = make_int4(outv[0], outv[1], outv[2], outv[3]);
        *(int4*)&g_off[base + 4] = make_int4(outv[4], outv[5], outv[6], outv[7]);
    }
    if (tid == 0) g_bsum[blockIdx.x] = total;
}

__global__ void k_scan2() {
    int tid = threadIdx.x;
    int v = (tid < NB) ? g_bsum[tid] : 0;
    int total;
    int e = block_exscan(v, tid, &total);
    if (tid < NB) g_bsum[tid] = e;
}

__global__ void k_scan3() {
    int t = blockIdx.x * blockDim.x + threadIdx.x;
    if (t < NT) {
        int v = g_off[t] + g_bsum[t / SCAN_TILE];
        g_off[t] = v;
        g_cur[t] = v;
    }
    if (t == 0) g_off[NT] = 2 * N_EDGES;
}

__global__ void k_permute(const int* __restrict__ eu, const int* __restrict__ ei,
                          const float* __restrict__ nrm) {
    int e = blockIdx.x * blockDim.x + threadIdx.x;
    if (e >= N_EDGES) return;
    int u = __ldg(eu + e);
    int i = __ldg(ei + e);
    int wbits = __float_as_int(__ldg(nrm + e));
    int s1 = atomicAdd(&g_cur[N_USERS + i], 1);   // item dst <- user src
    g_csr[s1] = make_int2(u, wbits);
    int s2 = atomicAdd(&g_cur[u], 1);             // user dst <- item src
    g_csr[s2] = make_int2(i, wbits);
}

// ---------------- propagation layer (gather, no atomics) ----------------

__global__ void k_layer(const float4* __restrict__ uf, const float4* __restrict__ itf,
                        int layer) {
    int t = blockIdx.x * blockDim.x + threadIdx.x;
    int n = t >> 4;
    int lane = t & 15;
    if (n >= NT) return;

    const float4* srcU = (layer == 0) ? uf  : g_u[layer - 1];
    const float4* srcI = (layer == 0) ? itf : g_i[layer - 1];
    const float4* src;
    float4* dst;
    if (n < N_USERS) { src = srcI; dst = &g_u[layer][n * DV + lane]; }
    else             { src = srcU; dst = &g_i[layer][(n - N_USERS) * DV + lane]; }

    int beg = __ldg(&g_off[n]);
    int end = __ldg(&g_off[n + 1]);

    float4 acc0 = make_float4(0.f, 0.f, 0.f, 0.f);
    float4 acc1 = make_float4(0.f, 0.f, 0.f, 0.f);
    int j = beg;
    for (; j + 1 < end; j += 2) {
        int2 p0 = __ldg(&g_csr[j]);
        int2 p1 = __ldg(&g_csr[j + 1]);
        float w0 = __int_as_float(p0.y);
        float w1 = __int_as_float(p1.y);
        float4 r0 = __ldg(&src[p0.x * DV + lane]);
        float4 r1 = __ldg(&src[p1.x * DV + lane]);
        acc0.x += r0.x * w0; acc0.y += r0.y * w0; acc0.z += r0.z * w0; acc0.w += r0.w * w0;
        acc1.x += r1.x * w1; acc1.y += r1.y * w1; acc1.z += r1.z * w1; acc1.w += r1.w * w1;
    }
    if (j < end) {
        int2 p0 = __ldg(&g_csr[j]);
        float w0 = __int_as_float(p0.y);
        float4 r0 = __ldg(&src[p0.x * DV + lane]);
        acc0.x += r0.x * w0; acc0.y += r0.y * w0; acc0.z += r0.z * w0; acc0.w += r0.w * w0;
    }
    *dst = make_float4(acc0.x + acc1.x, acc0.y + acc1.y,
                       acc0.z + acc1.z, acc0.w + acc1.w);
}

// ---------------- final batched lookup ----------------

__global__ void k_gather(const float4* __restrict__ uf, const float4* __restrict__ itf,
                         const int* __restrict__ users, const int* __restrict__ pos,
                         const int* __restrict__ neg, float4* __restrict__ out) {
    int t = blockIdx.x * blockDim.x + threadIdx.x;
    const int total = 3 * BATCH * DV;
    if (t >= total) return;
    int sec  = t / (BATCH * DV);
    int rem  = t % (BATCH * DV);
    int r    = rem / DV;
    int lane = rem % DV;

    float4 acc;
    if (sec == 0) {
        int idx = __ldg(users + r) * DV + lane;
        float4 a = uf[idx], b = g_u[0][idx], c = g_u[1][idx], d = g_u[2][idx];
        acc = make_float4(a.x + b.x + c.x + d.x, a.y + b.y + c.y + d.y,
                          a.z + b.z + c.z + d.z, a.w + b.w + c.w + d.w);
    } else {
        int idx = ((sec == 1) ? __ldg(pos + r) : __ldg(neg + r)) * DV + lane;
        float4 a = itf[idx], b = g_i[0][idx], c = g_i[1][idx], d = g_i[2][idx];
        acc = make_float4(a.x + b.x + c.x + d.x, a.y + b.y + c.y + d.y,
                          a.z + b.z + c.z + d.z, a.w + b.w + c.w + d.w);
    }
    const float s = 0.25f;
    out[t] = make_float4(acc.x * s, acc.y * s, acc.z * s, acc.w * s);
}

extern "C" void kernel_launch(void* const* d_in, const int* in_sizes, int n_in,
                              void* d_out, int out_size) {
    const float4* user_feat = (const float4*)d_in[0];
    const float4* item_feat = (const float4*)d_in[1];
    const int*    edge_u    = (const int*)d_in[2];
    const int*    edge_i    = (const int*)d_in[3];
    const float*  nrm       = (const float*)d_in[4];
    const int*    users     = (const int*)d_in[5];
    const int*    pos       = (const int*)d_in[6];
    const int*    neg       = (const int*)d_in[7];
    float4*       out       = (float4*)d_out;

    const int TPB = 256;

    k_zero_cnt<<<(NT + TPB - 1) / TPB, TPB>>>();
    k_hist<<<(N_EDGES + TPB - 1) / TPB, TPB>>>(edge_u, edge_i);
    k_scan1<<<NB, SCAN_TPB>>>();
    k_scan2<<<1, SCAN_TPB>>>();
    k_scan3<<<(NT + TPB - 1) / TPB, TPB>>>();
    k_permute<<<(N_EDGES + TPB - 1) / TPB, TPB>>>(edge_u, edge_i, nrm);

    const long long lt = (long long)NT * DV;
    const int layer_blocks = (int)((lt + TPB - 1) / TPB);
    for (int l = 0; l < 3; l++)
        k_layer<<<layer_blocks, TPB>>>(user_feat, item_feat, l);

    const int gt_total  = 3 * BATCH * DV;
    k_gather<<<(gt_total + TPB - 1) / TPB, TPB>>>(user_feat, item_feat, users, pos, neg, out);
}